// round 1
// baseline (speedup 1.0000x reference)
#include <cuda_runtime.h>

#define BB 64
#define TT 4096
#define HH 128
#define GG 384   /* 3H */

// Scratch (allocation-free rule: __device__ globals)
__device__ float g_y0[(size_t)BB * TT * HH];    // [b][t][k]   128 MiB
__device__ float g_xg1[(size_t)BB * TT * GG];   // [b][t][g]   402 MiB

typedef unsigned long long ull;

__device__ __forceinline__ ull pk(float a, float b) {
    ull r; asm("mov.b64 %0, {%1, %2};" : "=l"(r) : "f"(a), "f"(b)); return r;
}
__device__ __forceinline__ void upk(ull v, float& a, float& b) {
    asm("mov.b64 {%0, %1}, %2;" : "=f"(a), "=f"(b) : "l"(v));
}
// Packed fp32x2 FMA (Blackwell): 2 MACs per issue slot
__device__ __forceinline__ void ffma2(ull& acc, ull a, ull b) {
    asm("fma.rn.f32x2 %0, %1, %2, %0;" : "+l"(acc) : "l"(a), "l"(b));
}

__device__ __forceinline__ float sigf(float x) {
    return __fdividef(1.f, 1.f + __expf(-x));
}
__device__ __forceinline__ float tanhv(float x) {
    return 2.f * __fdividef(1.f, 1.f + __expf(-2.f * x)) - 1.f;
}

// Load one 128-float weight row into 64 packed register pairs.
__device__ __forceinline__ void loadw(ull* w, const float* __restrict__ row) {
    const float4* r4 = (const float4*)row;
#pragma unroll
    for (int i = 0; i < 32; i++) {
        float4 v = r4[i];
        w[2 * i]     = pk(v.x, v.y);
        w[2 * i + 1] = pk(v.z, v.w);
    }
}

// dot(w_row[128], hsm[128]) with broadcast LDS.128 + packed FMA, 4 acc chains.
__device__ __forceinline__ float dot128(const ull* w, const float* hsm) {
    const ulonglong2* h2 = (const ulonglong2*)hsm;
    ull a0 = 0, a1 = 0, a2 = 0, a3 = 0;
#pragma unroll
    for (int k = 0; k < 16; k++) {
        ulonglong2 p = h2[2 * k];
        ulonglong2 q = h2[2 * k + 1];
        ffma2(a0, w[4 * k + 0], p.x);
        ffma2(a1, w[4 * k + 1], p.y);
        ffma2(a2, w[4 * k + 2], q.x);
        ffma2(a3, w[4 * k + 3], q.y);
    }
    float x0, x1, y0, y1, z0, z1, u0, u1;
    upk(a0, x0, x1); upk(a1, y0, y1); upk(a2, z0, z1); upk(a3, u0, u1);
    return ((x0 + x1) + (y0 + y1)) + ((z0 + z1) + (u0 + u1));
}

// ---------------- Phase A: layer-0 recurrence (input dim 1) ----------------
__global__ void __launch_bounds__(384, 1)
k_layer0(const float* __restrict__ data, const float* __restrict__ hidden,
         const float* __restrict__ w_ih0, const float* __restrict__ w_hh0,
         const float* __restrict__ b_ih0, const float* __restrict__ b_hh0,
         float* __restrict__ hT) {
    __shared__ __align__(16) float hsm[HH];
    __shared__ float ssm[GG];
    __shared__ __align__(16) float xbuf[512];
    const int b = blockIdx.x, g = threadIdx.x;

    ull w[64];
    loadw(w, w_hh0 + g * HH);
    const float bhh = b_hh0[g];

    float wir = 0, wiz = 0, win = 0, bir = 0, biz = 0, bin = 0, hreg = 0;
    if (g < HH) {
        wir = w_ih0[g]; wiz = w_ih0[g + HH]; win = w_ih0[g + 2 * HH];
        bir = b_ih0[g]; biz = b_ih0[g + HH]; bin = b_ih0[g + 2 * HH];
        hreg = hidden[(size_t)b * HH + g];
        hsm[g] = hreg;
    }
    __syncthreads();

    const float* xg = data + (size_t)b * TT;
    float* y0 = g_y0 + (size_t)b * TT * HH;

    for (int t = 0; t < TT; t++) {
        if ((t & 511) == 0) {
            if (g < 128) ((float4*)xbuf)[g] = ((const float4*)(xg + t))[g];
        }
        float acc = dot128(w, hsm);
        ssm[g] = acc + bhh;
        __syncthreads();
        if (g < HH) {
            const float x = xbuf[t & 511];
            float r = sigf(fmaf(x, wir, bir) + ssm[g]);
            float z = sigf(fmaf(x, wiz, biz) + ssm[g + HH]);
            float n = tanhv(fmaf(x, win, bin) + r * ssm[g + 2 * HH]);
            hreg = (1.f - z) * n + z * hreg;
            hsm[g] = hreg;
            y0[(size_t)t * HH + g] = hreg;
        }
        __syncthreads();
    }
    if (g < HH) hT[(size_t)b * HH + g] = hreg;
}

// ---------------- Phase B: bulk xg1 = y0 @ w_ih1.T + b_ih1 ----------------
__global__ void __launch_bounds__(384, 1)
k_xg1(const float* __restrict__ w_ih1, const float* __restrict__ b_ih1) {
    __shared__ __align__(16) float ybuf[8 * HH];
    const int b = blockIdx.x >> 4;
    const int chunk = blockIdx.x & 15;
    const int g = threadIdx.x;

    ull w[64];
    loadw(w, w_ih1 + g * HH);
    const float bi = b_ih1[g];

    const float* y0 = g_y0 + (size_t)b * TT * HH;
    float* xo = g_xg1 + (size_t)b * TT * GG;
    const int t0 = chunk * 256;

    for (int tt = t0; tt < t0 + 256; tt += 8) {
        __syncthreads();
        if (g < 256) ((float4*)ybuf)[g] = ((const float4*)(y0 + (size_t)tt * HH))[g];
        __syncthreads();
#pragma unroll
        for (int r = 0; r < 8; r++) {
            float acc = dot128(w, ybuf + r * HH);
            xo[(size_t)(tt + r) * GG + g] = acc + bi;
        }
    }
}

// ---------- Phase C: layer-1 recurrence + fused ReLU->FC epilogue ----------
__global__ void __launch_bounds__(384, 1)
k_layer1(const float* __restrict__ hidden,
         const float* __restrict__ w_hh1, const float* __restrict__ b_hh1,
         const float* __restrict__ fc_w, const float* __restrict__ fc_b,
         float* __restrict__ out, float* __restrict__ hT) {
    __shared__ __align__(16) float hsm[HH];
    __shared__ float ssm[GG];
    __shared__ float xsm[GG];
    __shared__ float red[4];
    const int b = blockIdx.x, g = threadIdx.x;

    ull w[64];
    loadw(w, w_hh1 + g * HH);
    const float bhh = b_hh1[g];

    float hreg = 0, fw = 0;
    if (g < HH) {
        hreg = hidden[(size_t)BB * HH + (size_t)b * HH + g];
        hsm[g] = hreg;
        fw = fc_w[g];
    }
    const float fcb = fc_b[0];
    __syncthreads();

    const float* xgp = g_xg1 + (size_t)b * TT * GG + g;
    float* outp = out + (size_t)b * TT;

    float xv = xgp[0];
    for (int t = 0; t < TT; t++) {
        float xv_next = (t + 1 < TT) ? xgp[(size_t)(t + 1) * GG] : 0.f;  // prefetch
        float acc = dot128(w, hsm);
        ssm[g] = acc + bhh;
        xsm[g] = xv;
        __syncthreads();
        if (g < HH) {
            float r = sigf(xsm[g] + ssm[g]);
            float z = sigf(xsm[g + HH] + ssm[g + HH]);
            float n = tanhv(xsm[g + 2 * HH] + r * ssm[g + 2 * HH]);
            hreg = (1.f - z) * n + z * hreg;
            hsm[g] = hreg;
            float p = fmaxf(hreg, 0.f) * fw;
            p += __shfl_xor_sync(0xffffffffu, p, 16);
            p += __shfl_xor_sync(0xffffffffu, p, 8);
            p += __shfl_xor_sync(0xffffffffu, p, 4);
            p += __shfl_xor_sync(0xffffffffu, p, 2);
            p += __shfl_xor_sync(0xffffffffu, p, 1);
            if ((g & 31) == 0) red[g >> 5] = p;
        }
        __syncthreads();
        if (g == 0) outp[t] = (red[0] + red[1]) + (red[2] + red[3]) + fcb;
        xv = xv_next;
    }
    if (g < HH) hT[(size_t)b * HH + g] = hreg;
}

extern "C" void kernel_launch(void* const* d_in, const int* in_sizes, int n_in,
                              void* d_out, int out_size) {
    const float* data   = (const float*)d_in[0];
    const float* hidden = (const float*)d_in[1];
    const float* w_ih0  = (const float*)d_in[2];
    const float* w_hh0  = (const float*)d_in[3];
    const float* b_ih0  = (const float*)d_in[4];
    const float* b_hh0  = (const float*)d_in[5];
    const float* w_ih1  = (const float*)d_in[6];
    const float* w_hh1  = (const float*)d_in[7];
    const float* b_ih1  = (const float*)d_in[8];
    const float* b_hh1  = (const float*)d_in[9];
    const float* fc_w   = (const float*)d_in[10];
    const float* fc_b   = (const float*)d_in[11];

    float* out = (float*)d_out;
    float* hT0 = out + (size_t)BB * TT;        // hidden output, layer 0
    float* hT1 = hT0 + (size_t)BB * HH;        // hidden output, layer 1

    k_layer0<<<BB, 384>>>(data, hidden, w_ih0, w_hh0, b_ih0, b_hh0, hT0);
    k_xg1<<<BB * 16, 384>>>(w_ih1, b_ih1);
    k_layer1<<<BB, 384>>>(hidden, w_hh1, b_hh1, fc_w, fc_b, out, hT1);
}

// round 2
// speedup vs baseline: 1.0186x; 1.0186x over previous
#include <cuda_runtime.h>

#define BB 64
#define TT 4096
#define HH 128
#define GG 384   /* 3H */

// Scratch (allocation-free rule: __device__ globals)
__device__ float g_y0[(size_t)BB * TT * HH];    // [b][t][k]   128 MiB
__device__ float g_xg1[(size_t)BB * TT * GG];   // [b][t][g]   402 MiB

typedef unsigned long long ull;

static __device__ __forceinline__ ull pk(float a, float b) {
    ull r; asm("mov.b64 %0, {%1, %2};" : "=l"(r) : "f"(a), "f"(b)); return r;
}
static __device__ __forceinline__ void upk(ull v, float& a, float& b) {
    asm("mov.b64 {%0, %1}, %2;" : "=f"(a), "=f"(b) : "l"(v));
}
// Packed fp32x2 FMA (Blackwell): 2 MACs per issue slot
static __device__ __forceinline__ void ffma2(ull& acc, ull a, ull b) {
    asm("fma.rn.f32x2 %0, %1, %2, %0;" : "+l"(acc) : "l"(a), "l"(b));
}

static __device__ __forceinline__ float sigf(float x) {
    return __fdividef(1.f, 1.f + __expf(-x));
}
static __device__ __forceinline__ float tanhv(float x) {
    return 2.f * __fdividef(1.f, 1.f + __expf(-2.f * x)) - 1.f;
}

// Load one 128-float weight row into 64 packed register pairs.
static __device__ __forceinline__ void loadw(ull* w, const float* __restrict__ row) {
    const float4* r4 = (const float4*)row;
#pragma unroll
    for (int i = 0; i < 32; i++) {
        float4 v = r4[i];
        w[2 * i]     = pk(v.x, v.y);
        w[2 * i + 1] = pk(v.z, v.w);
    }
}

// dot(w_row[128], hsm[128]) with broadcast LDS.128 + packed FMA, 4 acc chains.
static __device__ __forceinline__ float dot128(const ull* w, const float* hsm) {
    const ulonglong2* h2 = (const ulonglong2*)hsm;
    ull a0 = 0, a1 = 0, a2 = 0, a3 = 0;
#pragma unroll
    for (int k = 0; k < 16; k++) {
        ulonglong2 p = h2[2 * k];
        ulonglong2 q = h2[2 * k + 1];
        ffma2(a0, w[4 * k + 0], p.x);
        ffma2(a1, w[4 * k + 1], p.y);
        ffma2(a2, w[4 * k + 2], q.x);
        ffma2(a3, w[4 * k + 3], q.y);
    }
    float x0, x1, y0, y1, z0, z1, u0, u1;
    upk(a0, x0, x1); upk(a1, y0, y1); upk(a2, z0, z1); upk(a3, u0, u1);
    return ((x0 + x1) + (y0 + y1)) + ((z0 + z1) + (u0 + u1));
}

// Thread layout for recurrent kernels:
//   warp = tid>>5, group g = warp/3 (4 groups), role = warp%3 (0=r,1=z,2=n)
//   Group g owns hidden units [32g, 32g+32); lane <-> unit within group.
//   Gate exchange: named barrier (g+1) over the 3 warps (96 threads) of the group.
//   h double-buffered in SMEM -> exactly ONE block-wide barrier per timestep.

// ---------------- Phase A: layer-0 recurrence (input dim 1) ----------------
__global__ void __launch_bounds__(384, 1)
k_layer0(const float* __restrict__ data, const float* __restrict__ hidden,
         const float* __restrict__ w_ih0, const float* __restrict__ w_hh0,
         const float* __restrict__ b_ih0, const float* __restrict__ b_hh0,
         float* __restrict__ hT) {
    __shared__ __align__(16) float hsm[2][HH];
    __shared__ float s_z[HH], s_hn[HH], s_xn[HH];
    __shared__ __align__(16) float xbuf[512];
    const int b = blockIdx.x, tid = threadIdx.x;
    const int warp = tid >> 5, lane = tid & 31;
    const int grp = warp / 3, role = warp - grp * 3;
    const int unit = (grp << 5) | lane;
    const int row = role * HH + unit;

    ull w[64];
    loadw(w, w_hh0 + row * HH);
    const float wi = w_ih0[row], bi = b_ih0[row], bh = b_hh0[row];

    float h_old = hidden[(size_t)b * HH + unit];
    if (role == 0) hsm[0][unit] = h_old;
    __syncthreads();

    const float* xg = data + (size_t)b * TT;
    float* y0 = g_y0 + (size_t)b * TT * HH;

    int cur = 0;
    for (int t = 0; t < TT; t++) {
        if ((t & 511) == 0) {
            if (tid < 128) ((float4*)xbuf)[tid] = ((const float4*)(xg + t))[tid];
            __syncthreads();
        }
        const float x = xbuf[t & 511];
        float acc = dot128(w, hsm[cur]) + bh;
        float xi = fmaf(x, wi, bi);
        float r_pre = acc + xi;                 // used by role 0
        if (role == 1) s_z[unit] = acc + xi;
        else if (role == 2) { s_hn[unit] = acc; s_xn[unit] = xi; }
        asm volatile("bar.sync %0, 96;" :: "r"(grp + 1) : "memory");
        if (role == 0) {
            float r = sigf(r_pre);
            float z = sigf(s_z[unit]);
            float n = tanhv(fmaf(r, s_hn[unit], s_xn[unit]));
            h_old = (1.f - z) * n + z * h_old;
            hsm[cur ^ 1][unit] = h_old;
        }
        __syncthreads();
        if (role == 0) y0[(size_t)t * HH + unit] = h_old;
        cur ^= 1;
    }
    if (role == 0) hT[(size_t)b * HH + unit] = h_old;
}

// ---------------- Phase B: bulk xg1 = y0 @ w_ih1.T + b_ih1 ----------------
__global__ void __launch_bounds__(384, 1)
k_xg1(const float* __restrict__ w_ih1, const float* __restrict__ b_ih1) {
    __shared__ __align__(16) float ybuf[8 * HH];
    const int b = blockIdx.x >> 4;
    const int chunk = blockIdx.x & 15;
    const int g = threadIdx.x;

    ull w[64];
    loadw(w, w_ih1 + g * HH);
    const float bi = b_ih1[g];

    const float* y0 = g_y0 + (size_t)b * TT * HH;
    float* xo = g_xg1 + (size_t)b * TT * GG;
    const int t0 = chunk * 256;

    for (int tt = t0; tt < t0 + 256; tt += 8) {
        __syncthreads();
        if (g < 256) ((float4*)ybuf)[g] = ((const float4*)(y0 + (size_t)tt * HH))[g];
        __syncthreads();
#pragma unroll
        for (int r = 0; r < 8; r++) {
            float acc = dot128(w, ybuf + r * HH);
            xo[(size_t)(tt + r) * GG + g] = acc + bi;
        }
    }
}

// ---------- Phase C: layer-1 recurrence + fused ReLU->FC epilogue ----------
__global__ void __launch_bounds__(384, 1)
k_layer1(const float* __restrict__ hidden,
         const float* __restrict__ w_hh1, const float* __restrict__ b_hh1,
         const float* __restrict__ fc_w, const float* __restrict__ fc_b,
         float* __restrict__ out, float* __restrict__ hT) {
    __shared__ __align__(16) float hsm[2][HH];
    __shared__ float s_z[HH], s_hn[HH], s_xn[HH];
    __shared__ float red[2][4];
    const int b = blockIdx.x, tid = threadIdx.x;
    const int warp = tid >> 5, lane = tid & 31;
    const int grp = warp / 3, role = warp - grp * 3;
    const int unit = (grp << 5) | lane;
    const int row = role * HH + unit;

    ull w[64];
    loadw(w, w_hh1 + row * HH);
    const float bh = b_hh1[row];
    const float fw = fc_w[unit];
    const float fcb = fc_b[0];

    float h_old = hidden[(size_t)BB * HH + (size_t)b * HH + unit];
    if (role == 0) hsm[0][unit] = h_old;
    __syncthreads();

    const float* xgp = g_xg1 + (size_t)b * TT * GG + row;
    float* outp = out + (size_t)b * TT;

    int cur = 0;
    float xv = xgp[0];
    float p = 0.f;
    for (int t = 0; t < TT; t++) {
        float acc = dot128(w, hsm[cur]) + bh;
        int tn = (t + 1 < TT) ? t + 1 : t;
        float xnext = xgp[(size_t)tn * GG];     // prefetch next step's x
        float pre = acc + xv;                   // role 0: r_pre
        if (role == 1) s_z[unit] = pre;
        else if (role == 2) { s_hn[unit] = acc; s_xn[unit] = xv; }
        asm volatile("bar.sync %0, 96;" :: "r"(grp + 1) : "memory");
        if (role == 0) {
            float r = sigf(pre);
            float z = sigf(s_z[unit]);
            float n = tanhv(fmaf(r, s_hn[unit], s_xn[unit]));
            h_old = (1.f - z) * n + z * h_old;
            hsm[cur ^ 1][unit] = h_old;
            p = fmaxf(h_old, 0.f) * fw;
        }
        __syncthreads();
        // Branchless butterfly (all warps run it; only leaders hold real p).
        // Independent of the next dot -> scheduler interleaves, off critical path.
        float q = p;
        q += __shfl_xor_sync(0xffffffffu, q, 16);
        q += __shfl_xor_sync(0xffffffffu, q, 8);
        q += __shfl_xor_sync(0xffffffffu, q, 4);
        q += __shfl_xor_sync(0xffffffffu, q, 2);
        q += __shfl_xor_sync(0xffffffffu, q, 1);
        if (role == 0 && lane == 0) red[t & 1][grp] = q;
        if (t > 0 && tid == 0) {
            const float* rd = red[(t - 1) & 1];
            outp[t - 1] = ((rd[0] + rd[1]) + (rd[2] + rd[3])) + fcb;
        }
        xv = xnext;
        cur ^= 1;
    }
    __syncthreads();
    if (tid == 0) {
        const float* rd = red[(TT - 1) & 1];
        outp[TT - 1] = ((rd[0] + rd[1]) + (rd[2] + rd[3])) + fcb;
    }
    if (role == 0) hT[(size_t)b * HH + unit] = h_old;
}

extern "C" void kernel_launch(void* const* d_in, const int* in_sizes, int n_in,
                              void* d_out, int out_size) {
    const float* data   = (const float*)d_in[0];
    const float* hidden = (const float*)d_in[1];
    const float* w_ih0  = (const float*)d_in[2];
    const float* w_hh0  = (const float*)d_in[3];
    const float* b_ih0  = (const float*)d_in[4];
    const float* b_hh0  = (const float*)d_in[5];
    const float* w_ih1  = (const float*)d_in[6];
    const float* w_hh1  = (const float*)d_in[7];
    const float* b_ih1  = (const float*)d_in[8];
    const float* b_hh1  = (const float*)d_in[9];
    const float* fc_w   = (const float*)d_in[10];
    const float* fc_b   = (const float*)d_in[11];

    float* out = (float*)d_out;
    float* hT0 = out + (size_t)BB * TT;        // hidden output, layer 0
    float* hT1 = hT0 + (size_t)BB * HH;        // hidden output, layer 1

    k_layer0<<<BB, 384>>>(data, hidden, w_ih0, w_hh0, b_ih0, b_hh0, hT0);
    k_xg1<<<BB * 16, 384>>>(w_ih1, b_ih1);
    k_layer1<<<BB, 384>>>(hidden, w_hh1, b_hh1, fc_w, fc_b, out, hT1);
}